// round 15
// baseline (speedup 1.0000x reference)
#include <cuda_runtime.h>
#include <math.h>
#include <stdint.h>

typedef unsigned long long ull;
typedef unsigned int u32;
typedef unsigned short u16;

#define NNODE 307
#define NP    320
#define BATCH 512
#define CIN   5
#define HID   16
#define KORD  6
#define BH    8192          // BATCH*HID
#define BC    2560          // BATCH*CIN
#define NPBC  (NP*BC)

// ------------------------------ scratch ------------------------------------
__device__ __align__(256) float g_En[NNODE * 10];
__device__ __align__(256) float g_dinv[NNODE];
__device__ __align__(256) float g_L[NP * NP];
__device__ __align__(256) u16 g_Lhi[NP * NP];
__device__ __align__(256) u16 g_Llo[NP * NP];
__device__ __align__(256) float g_Y[KORD * NPBC];
__device__ __align__(256) float g_SA[NP * BH];
__device__ __align__(256) float g_SB[NP * BH];
__device__ __align__(256) float g_T[NP * BH];
__device__ __align__(256) float g_U[NP * BH];

// ------------------------------ helpers ------------------------------------
__device__ __forceinline__ ull pack2(float x, float y) {
    ull d; asm("mov.b64 %0, {%1, %2};" : "=l"(d) : "f"(x), "f"(y)); return d;
}
__device__ __forceinline__ void unpack2(ull v, float& x, float& y) {
    asm("mov.b64 {%0, %1}, %2;" : "=f"(x), "=f"(y) : "l"(v));
}
__device__ __forceinline__ ull fma2(ull a, ull b, ull c) {
    ull d; asm("fma.rn.f32x2 %0, %1, %2, %3;" : "=l"(d) : "l"(a), "l"(b), "l"(c));
    return d;
}
__device__ __forceinline__ float ftanh(float x) {
    float e; asm("ex2.approx.f32 %0, %1;" : "=f"(e) : "f"(x * 2.885390082f));
    float r; asm("rcp.approx.f32 %0, %1;" : "=f"(r) : "f"(e + 1.0f));
    return fmaf(-2.0f, r, 1.0f);
}
__device__ __forceinline__ float fsig(float x) {
    return fmaf(0.5f, ftanh(0.5f * x), 0.5f);
}
__device__ __forceinline__ u32 smem_u32(const void* p) {
    u32 a;
    asm("{ .reg .u64 t; cvta.to.shared.u64 t, %1; cvt.u32.u64 %0, t; }"
        : "=r"(a) : "l"(p));
    return a;
}
__device__ __forceinline__ void hmma(float* d, const u32* a, u32 b0, u32 b1) {
    asm volatile("mma.sync.aligned.m16n8k16.row.col.f32.bf16.bf16.f32 "
        "{%0,%1,%2,%3}, {%4,%5,%6,%7}, {%8,%9}, {%0,%1,%2,%3};"
        : "+f"(d[0]), "+f"(d[1]), "+f"(d[2]), "+f"(d[3])
        : "r"(a[0]), "r"(a[1]), "r"(a[2]), "r"(a[3]), "r"(b0), "r"(b1));
}
__device__ __forceinline__ void ldsm4(u32* r, u32 addr) {
    asm volatile("ldmatrix.sync.aligned.m8n8.x4.shared.b16 {%0,%1,%2,%3}, [%4];"
        : "=r"(r[0]), "=r"(r[1]), "=r"(r[2]), "=r"(r[3]) : "r"(addr));
}
__device__ __forceinline__ void ldsm4t(u32* r, u32 addr) {
    asm volatile("ldmatrix.sync.aligned.m8n8.x4.trans.shared.b16 {%0,%1,%2,%3}, [%4];"
        : "=r"(r[0]), "=r"(r[1]), "=r"(r[2]), "=r"(r[3]) : "r"(addr));
}

// ------------------------------ setup ---------------------------------------
__global__ void __launch_bounds__(320) k_norm(const float* __restrict__ E) {
    __shared__ float sSum[10];
    int t = threadIdx.x;
    if (t < 10) sSum[t] = 0.f;
    __syncthreads();
    float e[10];
    if (t < NNODE) {
        float s = 0.f;
#pragma unroll
        for (int c = 0; c < 10; c++) { e[c] = E[t * 10 + c]; s += e[c] * e[c]; }
        float inv = rsqrtf(s);
#pragma unroll
        for (int c = 0; c < 10; c++) {
            e[c] *= inv;
            g_En[t * 10 + c] = e[c];
            atomicAdd(&sSum[c], e[c]);
        }
    }
    __syncthreads();
    if (t < NNODE) {
        float d = 0.f;
#pragma unroll
        for (int c = 0; c < 10; c++) d += e[c] * sSum[c];
        g_dinv[t] = rsqrtf(d);
    }
}

__global__ void k_lap() {
    int idx = blockIdx.x * 256 + threadIdx.x;
    if (idx >= NP * NP) return;
    int n = idx / NP, m = idx % NP;
    float v = 0.f;
    if (n < NNODE && m < NNODE) {
        float dot = 0.f;
#pragma unroll
        for (int c = 0; c < 10; c++) dot += g_En[n * 10 + c] * g_En[m * 10 + c];
        v = ((n == m) ? 1.f : 0.f) - g_dinv[n] * dot * g_dinv[m];
    }
    g_L[idx] = v;
    u32 bits = __float_as_uint(v);
    float res = v - __uint_as_float(bits & 0xFFFF0000u);
    u16 lo16;
    asm("cvt.rn.bf16.f32 %0, %1;" : "=h"(lo16) : "f"(res));
    g_Lhi[idx] = (u16)(bits >> 16);
    g_Llo[idx] = lo16;
}

__global__ void k_xt(const float* __restrict__ flow, float* __restrict__ Y0) {
    int idx = blockIdx.x * 128 + threadIdx.x;
    if (idx >= NP * BATCH) return;
    int n = idx >> 9, b = idx & 511;
#pragma unroll
    for (int c = 0; c < CIN; c++) {
        float v = 0.f;
        if (n < NNODE) v = flow[((size_t)b * NNODE + n) * CIN + c];
        Y0[(size_t)n * BC + b * CIN + c] = v;
    }
}

// ====== shared HMMA mainloop: 64x64 tile, K32 double-chunk staging ==========
// Sub-tile (bytes): Ah[64x24]=3072, Al=3072, Bh[16x72]=2304, Bl=2304 -> 10752.
// Stage = 2 sub-tiles = 21504. Two stages = 43008. 10 barriers for K=320.
#define HMMA_SUB 10752
#define HMMA_ST  21504
__device__ __forceinline__ void hmma_subcompute(
    u32 stg, int warp, int lane, float acc[8][4])
{
    u32 aoff = stg + (u32)((warp * 16 + (lane & 15)) * 48 + (lane >> 4) * 16);
    u32 ah[4], al[4];
    ldsm4(ah, aoff);
    ldsm4(al, aoff + 3072);
#pragma unroll
    for (int nt = 0; nt < 4; nt++) {
        u32 boff = stg + 6144 +
            (u32)((lane & 15) * 144 + (nt * 16 + ((lane >> 4) & 1) * 8) * 2);
        u32 bh[4], bl[4];
        ldsm4t(bh, boff);
        ldsm4t(bl, boff + 2304);
        hmma(acc[2 * nt],     ah, bh[0], bh[1]);
        hmma(acc[2 * nt],     ah, bl[0], bl[1]);
        hmma(acc[2 * nt],     al, bh[0], bh[1]);
        hmma(acc[2 * nt + 1], ah, bh[2], bh[3]);
        hmma(acc[2 * nt + 1], ah, bl[2], bl[3]);
        hmma(acc[2 * nt + 1], al, bh[2], bh[3]);
    }
}

__device__ __forceinline__ void hmma_mainloop(
    const float* __restrict__ Bsrc, int ld, int m0, int col0,
    char* smraw, float acc[8][4])
{
    int tid = threadIdx.x;
    int lane = tid & 31, warp = tid >> 5;
    int a_row = tid >> 1, a_half = tid & 1;
    int b_row = tid >> 3, b_seg = tid & 7;
    const u16* Aph = g_Lhi + (size_t)(m0 + a_row) * NP + a_half * 8;
    const u16* Apl = g_Llo + (size_t)(m0 + a_row) * NP + a_half * 8;
    const float* Bp = Bsrc + (size_t)b_row * ld + col0 + b_seg * 8;
    u32 smbase = smem_u32(smraw);

    // loads K16-tiles 2*tp and 2*tp+1 into stage st (LDGs batched first)
    auto load_pair = [&](int tp, int st) {
        char* s0 = smraw + st * HMMA_ST;
        char* s1 = s0 + HMMA_SUB;
        int k0 = 2 * tp, k1 = 2 * tp + 1;
        uint4 ah0 = *(const uint4*)(Aph + k0 * 16);
        uint4 al0 = *(const uint4*)(Apl + k0 * 16);
        uint4 ah1 = *(const uint4*)(Aph + k1 * 16);
        uint4 al1 = *(const uint4*)(Apl + k1 * 16);
        const float* bp0 = Bp + (size_t)(k0 * 16) * ld;
        const float* bp1 = Bp + (size_t)(k1 * 16) * ld;
        float4 b00 = ((const float4*)bp0)[0];
        float4 b01 = ((const float4*)bp0)[1];
        float4 b10 = ((const float4*)bp1)[0];
        float4 b11 = ((const float4*)bp1)[1];
        *(uint4*)(s0 + a_row * 48 + a_half * 16) = ah0;
        *(uint4*)(s0 + 3072 + a_row * 48 + a_half * 16) = al0;
        *(uint4*)(s1 + a_row * 48 + a_half * 16) = ah1;
        *(uint4*)(s1 + 3072 + a_row * 48 + a_half * 16) = al1;
        float f0[8] = {b00.x, b00.y, b00.z, b00.w, b01.x, b01.y, b01.z, b01.w};
        float f1[8] = {b10.x, b10.y, b10.z, b10.w, b11.x, b11.y, b11.z, b11.w};
        u32 hi0[4], lo0[4], hi1[4], lo1[4];
#pragma unroll
        for (int q = 0; q < 4; q++) {
            u32 ba = __float_as_uint(f0[2 * q]);
            u32 bb = __float_as_uint(f0[2 * q + 1]);
            asm("prmt.b32 %0, %1, %2, 0x7632;" : "=r"(hi0[q]) : "r"(ba), "r"(bb));
            float ra = f0[2 * q]     - __uint_as_float(ba & 0xFFFF0000u);
            float rb = f0[2 * q + 1] - __uint_as_float(bb & 0xFFFF0000u);
            asm("cvt.rn.bf16x2.f32 %0, %1, %2;" : "=r"(lo0[q]) : "f"(rb), "f"(ra));
            u32 bc = __float_as_uint(f1[2 * q]);
            u32 bd = __float_as_uint(f1[2 * q + 1]);
            asm("prmt.b32 %0, %1, %2, 0x7632;" : "=r"(hi1[q]) : "r"(bc), "r"(bd));
            float rc = f1[2 * q]     - __uint_as_float(bc & 0xFFFF0000u);
            float rd = f1[2 * q + 1] - __uint_as_float(bd & 0xFFFF0000u);
            asm("cvt.rn.bf16x2.f32 %0, %1, %2;" : "=r"(lo1[q]) : "f"(rd), "f"(rc));
        }
        *(uint4*)(s0 + 6144 + b_row * 144 + b_seg * 16) = make_uint4(hi0[0], hi0[1], hi0[2], hi0[3]);
        *(uint4*)(s0 + 8448 + b_row * 144 + b_seg * 16) = make_uint4(lo0[0], lo0[1], lo0[2], lo0[3]);
        *(uint4*)(s1 + 6144 + b_row * 144 + b_seg * 16) = make_uint4(hi1[0], hi1[1], hi1[2], hi1[3]);
        *(uint4*)(s1 + 8448 + b_row * 144 + b_seg * 16) = make_uint4(lo1[0], lo1[1], lo1[2], lo1[3]);
    };

    load_pair(0, 0);
    __syncthreads();

#pragma unroll 1
    for (int tp = 0; tp < 10; tp++) {
        int cur = tp & 1;
        if (tp < 9) load_pair(tp + 1, cur ^ 1);
        u32 stg = smbase + cur * HMMA_ST;
        hmma_subcompute(stg, warp, lane, acc);
        hmma_subcompute(stg + HMMA_SUB, warp, lane, acc);
        __syncthreads();
    }
}

// ---- cheb: Cout = alpha*(L@Bin) + beta*Csub, HMMA path ---------------------
__global__ void __launch_bounds__(128) k_mm(
    const float* __restrict__ Bin, const float* __restrict__ Csub,
    float* __restrict__ Cout, int ld, float alpha, float beta)
{
    __shared__ __align__(16) char smraw[43008];
    int tid = threadIdx.x;
    int lane = tid & 31, warp = tid >> 5;
    int m0 = blockIdx.y * 64, col0 = blockIdx.x * 64;
    float acc[8][4];
#pragma unroll
    for (int j = 0; j < 8; j++)
#pragma unroll
        for (int q = 0; q < 4; q++) acc[j][q] = 0.f;
    hmma_mainloop(Bin, ld, m0, col0, smraw, acc);

    int r0 = m0 + warp * 16 + (lane >> 2);
    int c0 = col0 + (lane & 3) * 2;
#pragma unroll
    for (int j = 0; j < 8; j++) {
        size_t oa = (size_t)r0 * ld + c0 + j * 8;
        size_t ob = (size_t)(r0 + 8) * ld + c0 + j * 8;
        float2 ca = *(const float2*)(Csub + oa);
        float2 cb = *(const float2*)(Csub + ob);
        *(float2*)(Cout + oa) = make_float2(alpha * acc[j][0] + beta * ca.x,
                                            alpha * acc[j][1] + beta * ca.y);
        *(float2*)(Cout + ob) = make_float2(alpha * acc[j][2] + beta * cb.x,
                                            alpha * acc[j][3] + beta * cb.y);
    }
}

// -------- combine: SB = sum_k Y_k @ cheb_w[k] + cheb_b ; SA = Y_0 @ cou_w ---
__global__ void __launch_bounds__(128) k_combine(
    const float* __restrict__ cheb_w, const float* __restrict__ cheb_b,
    const float* __restrict__ cou_w, const float* __restrict__ Y,
    float* __restrict__ SA, float* __restrict__ SB)
{
    __shared__ float scw[KORD * CIN * HID];
    __shared__ float scb[HID];
    __shared__ float sco[CIN * HID];
    int tid = threadIdx.x;
    for (int i = tid; i < KORD * CIN * HID; i += 128) scw[i] = cheb_w[i];
    if (tid < HID) scb[tid] = cheb_b[tid];
    if (tid < CIN * HID) sco[tid] = cou_w[tid];
    __syncthreads();
    int idx = blockIdx.x * 128 + tid;
    if (idx >= NP * BATCH) return;
    int n = idx >> 9, b = idx & 511;
    size_t base = (size_t)n * BH + (b << 4);
    if (n >= NNODE) {
#pragma unroll
        for (int h = 0; h < 16; h++) { SA[base + h] = 0.f; SB[base + h] = 0.f; }
        return;
    }
    float o[16], p[16];
#pragma unroll
    for (int h = 0; h < 16; h++) { o[h] = scb[h]; p[h] = 0.f; }
#pragma unroll
    for (int k = 0; k < KORD; k++) {
#pragma unroll
        for (int c = 0; c < CIN; c++) {
            float y = Y[(size_t)k * NPBC + (size_t)n * BC + b * CIN + c];
            const float* w = &scw[(k * CIN + c) * HID];
#pragma unroll
            for (int h = 0; h < 16; h++) o[h] = fmaf(y, w[h], o[h]);
            if (k == 0) {
#pragma unroll
                for (int h = 0; h < 16; h++) p[h] = fmaf(y, sco[c * HID + h], p[h]);
            }
        }
    }
#pragma unroll
    for (int h = 0; h < 16; h++) { SB[base + h] = o[h]; SA[base + h] = p[h]; }
}

// ======== GL via mma.sync bf16 split-precision ==============================
__global__ void __launch_bounds__(128) k_gl(
    const float* __restrict__ X, const float* __restrict__ A1,
    const float* __restrict__ A2,
    float* __restrict__ O1, float* __restrict__ O2,
    const float* __restrict__ w1, const float* __restrict__ w2,
    const float* __restrict__ w3, const float* __restrict__ b3, int mode)
{
    __shared__ __align__(16) char smraw[43008];
    __shared__ float sw1[256], sw2[256], sw3[256], sb3[16];
    int tid = threadIdx.x;
    int lane = tid & 31, warp = tid >> 5;
    for (int i = tid; i < 256; i += 128) { sw1[i] = w1[i]; sw2[i] = w2[i]; sw3[i] = w3[i]; }
    if (tid < 16) sb3[tid] = b3[tid];

    int m0 = blockIdx.y * 64, col0 = blockIdx.x * 64;
    float acc[8][4];
#pragma unroll
    for (int j = 0; j < 8; j++)
#pragma unroll
        for (int q = 0; q < 4; q++) acc[j][q] = 0.f;
    hmma_mainloop(X, BH, m0, col0, smraw, acc);

    // stage o1 = L@X into smem (alias; stride 72 floats)
    float* o1s = (float*)smraw;
    {
        int r0 = warp * 16 + (lane >> 2);
        int c = (lane & 3) * 2;
#pragma unroll
        for (int j = 0; j < 8; j++) {
            *(float2*)&o1s[r0 * 72 + j * 8 + c]       = make_float2(acc[j][0], acc[j][1]);
            *(float2*)&o1s[(r0 + 8) * 72 + j * 8 + c] = make_float2(acc[j][2], acc[j][3]);
        }
    }
    __syncthreads();

    // epilogue: 256 items = 64 rows x 4 col-groups ; 2 per thread
#pragma unroll 1
    for (int it = 0; it < 2; it++) {
        int item = it * 128 + tid;
        int r = item >> 2, bl = item & 3;
        size_t base = (size_t)(m0 + r) * BH + col0 + (bl << 4);
        float xv[16];
#pragma unroll
        for (int q = 0; q < 4; q++) {
            float4 v = *(const float4*)(X + base + 4 * q);
            xv[4 * q] = v.x; xv[4 * q + 1] = v.y; xv[4 * q + 2] = v.z; xv[4 * q + 3] = v.w;
        }
        float a1v[16];
#pragma unroll 4
        for (int p = 0; p < 16; p++) {
            float s = 0.f;
#pragma unroll
            for (int h = 0; h < 16; h++) s = fmaf(xv[h], sw1[h * 16 + p], s);
            a1v[p] = ftanh(s);
        }
        float a2v[16];
#pragma unroll 4
        for (int p = 0; p < 16; p++) {
            float s = 0.f;
#pragma unroll
            for (int h = 0; h < 16; h++) s = fmaf(a1v[h], sw2[h * 16 + p], s);
            a2v[p] = ftanh(s);
        }
        float rr[16];
        const float* o1p = o1s + r * 72 + (bl << 4);
#pragma unroll
        for (int h = 0; h < 16; h++) rr[h] = o1p[h] - a2v[h];
        if (mode == 0) {
#pragma unroll 4
            for (int p = 0; p < 16; p++) {
                float s = sb3[p];
#pragma unroll
                for (int h = 0; h < 16; h++) s = fmaf(rr[h], sw3[h * 16 + p], s);
                O1[base + p] = s;
                O2[base + p] = A1[base + p] + 2.0f * s;
            }
        } else {
#pragma unroll 4
            for (int p = 0; p < 16; p++) {
                float s = sb3[p];
#pragma unroll
                for (int h = 0; h < 16; h++) s = fmaf(rr[h], sw3[h * 16 + p], s);
                O1[base + p] = A1[base + p] + 0.5f * A2[base + p] + 0.5f * s;
            }
        }
    }
}

// ---------------- 16x16 matmul helper with f32x2 ----------------------------
__device__ __forceinline__ void mm16_f2(const float* x, const float* Wsh,
                                        const ull* bias2, float* out)
{
    const ull* W2 = (const ull*)Wsh;
    ull xs[16];
#pragma unroll
    for (int h = 0; h < 16; h++) xs[h] = pack2(x[h], x[h]);
#pragma unroll
    for (int pp = 0; pp < 8; pp++) {
        ull s = bias2 ? bias2[pp] : pack2(0.f, 0.f);
#pragma unroll
        for (int h = 0; h < 16; h++) s = fma2(xs[h], W2[h * 8 + pp], s);
        unpack2(s, out[2 * pp], out[2 * pp + 1]);
    }
}

// ---------------- NL: fused 10-step LSTM-cell chain (f32x2) -----------------
__device__ __forceinline__ void nl_eval(
    const float* x, float* out,
    const ull* W2, const ull* sb2, const ull* w22)
{
    ull xs[16];
#pragma unroll
    for (int h = 0; h < 16; h++) xs[h] = pack2(x[h], x[h]);
    ull acc2[8];
#pragma unroll
    for (int q = 0; q < 8; q++) acc2[q] = pack2(0.f, 0.f);
#pragma unroll 1
    for (int pp = 0; pp < 16; pp++) {
        ull gi = sb2[pp], gg = sb2[32 + pp], go = sb2[48 + pp];
#pragma unroll
        for (int h = 0; h < 16; h++) {
            gi = fma2(xs[h], W2[h * 64 + pp], gi);
            gg = fma2(xs[h], W2[h * 64 + 32 + pp], gg);
            go = fma2(xs[h], W2[h * 64 + 48 + pp], go);
        }
        float gi0, gi1, gg0, gg1, go0, go1;
        unpack2(gi, gi0, gi1); unpack2(gg, gg0, gg1); unpack2(go, go0, go1);
        float c0 = fsig(gi0) * ftanh(gg0);
        float th0 = ftanh(fsig(go0) * ftanh(c0));
        float c1 = fsig(gi1) * ftanh(gg1);
        float th1 = ftanh(fsig(go1) * ftanh(c1));
        ull t0 = pack2(th0, th0), t1 = pack2(th1, th1);
#pragma unroll
        for (int q = 0; q < 8; q++) {
            acc2[q] = fma2(t0, w22[(2 * pp) * 8 + q], acc2[q]);
            acc2[q] = fma2(t1, w22[(2 * pp + 1) * 8 + q], acc2[q]);
        }
    }
#pragma unroll
    for (int q = 0; q < 8; q++) unpack2(acc2[q], out[2 * q], out[2 * q + 1]);
}

__global__ void __launch_bounds__(128) k_nl(
    const float* __restrict__ S0, const float* __restrict__ S1,
    const float* __restrict__ Wih, const float* __restrict__ lb,
    const float* __restrict__ w2, const float* __restrict__ cw,
    const float* __restrict__ cb, const float* __restrict__ c1w,
    const float* __restrict__ c1b, float* __restrict__ out)
{
    __shared__ __align__(16) float sW[16 * 128];
    __shared__ __align__(16) float sb[128];
    __shared__ __align__(16) float sw2[32 * 16];
    __shared__ __align__(16) float scw[256], sc1w[256];
    __shared__ __align__(16) float scb[16], sc1b[16];
    int tid = threadIdx.x;
    for (int i = tid; i < 2048; i += 128) sW[i] = Wih[i];
    sb[tid] = lb[tid];
    for (int i = tid; i < 512; i += 128) sw2[i] = w2[i];
    for (int i = tid; i < 256; i += 128) { scw[i] = cw[i]; sc1w[i] = c1w[i]; }
    if (tid < 16) { scb[tid] = cb[tid]; sc1b[tid] = c1b[tid]; }
    __syncthreads();
    const ull* W2  = (const ull*)sW;
    const ull* sb2 = (const ull*)sb;
    const ull* w22 = (const ull*)sw2;

    int idx = blockIdx.x * 128 + tid;
    int n = idx >> 9, b = idx & 511;
    size_t base = (size_t)n * BH + ((size_t)b << 4);
    float s0[16], s1[16];
#pragma unroll
    for (int q = 0; q < 4; q++) {
        float4 t0 = *(const float4*)(S0 + base + 4 * q);
        float4 t1 = *(const float4*)(S1 + base + 4 * q);
        s0[4 * q] = t0.x; s0[4 * q + 1] = t0.y; s0[4 * q + 2] = t0.z; s0[4 * q + 3] = t0.w;
        s1[4 * q] = t1.x; s1[4 * q + 1] = t1.y; s1[4 * q + 2] = t1.z; s1[4 * q + 3] = t1.w;
    }
    float s00[16], s11[16];
    mm16_f2(s0, scw, (const ull*)scb, s00);
    mm16_f2(s1, sc1w, (const ull*)sc1b, s11);
    float* op = out + (((size_t)b * NNODE + n) * 10) * HID;
    float t[16], tmp[16], g[16], p2[16];
    nl_eval(s11, t, W2, sb2, w22);
#pragma unroll
    for (int h = 0; h < 16; h++) tmp[h] = fmaf(2.0f, t[h], s00[h]);
    nl_eval(tmp, tmp, W2, sb2, w22);
#pragma unroll
    for (int h = 0; h < 16; h++) {
        g[h] = fmaf(0.5f, t[h], s1[h]) + 0.5f * tmp[h];
        p2[h] = s11[h];
    }
#pragma unroll
    for (int q = 0; q < 4; q++)
        *(float4*)(op + 4 * q) = make_float4(g[4 * q], g[4 * q + 1], g[4 * q + 2], g[4 * q + 3]);
#pragma unroll 1
    for (int j = 1; j < 10; j++) {
        nl_eval(g, t, W2, sb2, w22);
#pragma unroll
        for (int h = 0; h < 16; h++) tmp[h] = fmaf(2.0f, t[h], p2[h]);
        nl_eval(tmp, tmp, W2, sb2, w22);
#pragma unroll
        for (int h = 0; h < 16; h++) {
            float nw = fmaf(0.5f, t[h], g[h]) + 0.5f * tmp[h];
            p2[h] = g[h];
            g[h] = nw;
        }
        float* oj = op + (size_t)j * HID;
#pragma unroll
        for (int q = 0; q < 4; q++)
            *(float4*)(oj + 4 * q) = make_float4(g[4 * q], g[4 * q + 1], g[4 * q + 2], g[4 * q + 3]);
    }
}

// ------------------------------ launch --------------------------------------
extern "C" void kernel_launch(void* const* d_in, const int* in_sizes, int n_in,
                              void* d_out, int out_size) {
    const float* flow    = (const float*)d_in[0];
    const float* nodeemb = (const float*)d_in[1];
    const float* cheb_w  = (const float*)d_in[2];
    const float* cheb_b  = (const float*)d_in[3];
    const float* cou_w   = (const float*)d_in[4];
    const float* gl_out  = (const float*)d_in[5];
    const float* gl_fk   = (const float*)d_in[6];
    const float* gl_tz_w = (const float*)d_in[7];
    const float* gl_tz_b = (const float*)d_in[8];
    const float* lstmW   = (const float*)d_in[9];
    const float* lstmb   = (const float*)d_in[10];
    const float* nl_w2   = (const float*)d_in[11];
    const float* c_w     = (const float*)d_in[12];
    const float* c_b     = (const float*)d_in[13];
    const float* c1_w    = (const float*)d_in[14];
    const float* c1_b    = (const float*)d_in[15];

    float *Y, *SA, *SB, *T, *U;
    cudaGetSymbolAddress((void**)&Y,  g_Y);
    cudaGetSymbolAddress((void**)&SA, g_SA);
    cudaGetSymbolAddress((void**)&SB, g_SB);
    cudaGetSymbolAddress((void**)&T,  g_T);
    cudaGetSymbolAddress((void**)&U,  g_U);

    k_xt<<<(NP * BATCH + 127) / 128, 128>>>(flow, Y);
    k_norm<<<1, 320>>>(nodeemb);
    k_lap<<<(NP * NP + 255) / 256, 256>>>();

    // Chebyshev feature recurrence on tensor cores
    dim3 cgrid(BC / 64, NP / 64);
    k_mm<<<cgrid, 128>>>(Y, Y, Y + NPBC, BC, 1.f, 0.f);
    for (int k = 2; k < KORD; k++)
        k_mm<<<cgrid, 128>>>(
            Y + (size_t)(k - 1) * NPBC, Y + (size_t)(k - 2) * NPBC,
            Y + (size_t)k * NPBC, BC, 2.f, -1.f);

    k_combine<<<(NP * BATCH + 127) / 128, 128>>>(cheb_w, cheb_b, cou_w, Y, SA, SB);

    // GL diffusion chain (HMMA path)
    float* p = SA;
    float* c = SB;
    dim3 glgrid(BH / 64, NP / 64);
    for (int it = 0; it < 10; it++) {
        k_gl<<<glgrid, 128>>>(c, p, p, T, U, gl_out, gl_fk, gl_tz_w, gl_tz_b, 0);
        k_gl<<<glgrid, 128>>>(U, c, T, p, T, gl_out, gl_fk, gl_tz_w, gl_tz_b, 1);
        float* tmpp = p; p = c; c = tmpp;
    }
    // after 10 iters: step_0 = p, step_1 = c

    k_nl<<<(NNODE * BATCH) / 128, 128>>>(p, c, lstmW, lstmb, nl_w2,
                                         c_w, c_b, c1_w, c1_b, (float*)d_out);
}

// round 16
// speedup vs baseline: 1.0042x; 1.0042x over previous
#include <cuda_runtime.h>
#include <math.h>
#include <stdint.h>

typedef unsigned long long ull;
typedef unsigned int u32;
typedef unsigned short u16;

#define NNODE 307
#define NP    320
#define BATCH 512
#define CIN   5
#define HID   16
#define KORD  6
#define BH    8192          // BATCH*HID
#define BC    2560          // BATCH*CIN
#define NPBC  (NP*BC)

// ------------------------------ scratch ------------------------------------
__device__ __align__(256) float g_En[NNODE * 10];
__device__ __align__(256) float g_dinv[NNODE];
__device__ __align__(256) float g_L[NP * NP];
__device__ __align__(256) u16 g_Lhi[NP * NP];
__device__ __align__(256) u16 g_Llo[NP * NP];
__device__ __align__(256) float g_Y[KORD * NPBC];
__device__ __align__(256) float g_SA[NP * BH];
__device__ __align__(256) float g_SB[NP * BH];
__device__ __align__(256) float g_T[NP * BH];
__device__ __align__(256) float g_U[NP * BH];

// ------------------------------ helpers ------------------------------------
__device__ __forceinline__ ull pack2(float x, float y) {
    ull d; asm("mov.b64 %0, {%1, %2};" : "=l"(d) : "f"(x), "f"(y)); return d;
}
__device__ __forceinline__ void unpack2(ull v, float& x, float& y) {
    asm("mov.b64 {%0, %1}, %2;" : "=f"(x), "=f"(y) : "l"(v));
}
__device__ __forceinline__ ull fma2(ull a, ull b, ull c) {
    ull d; asm("fma.rn.f32x2 %0, %1, %2, %3;" : "=l"(d) : "l"(a), "l"(b), "l"(c));
    return d;
}
__device__ __forceinline__ float ftanh(float x) {
    float e; asm("ex2.approx.f32 %0, %1;" : "=f"(e) : "f"(x * 2.885390082f));
    float r; asm("rcp.approx.f32 %0, %1;" : "=f"(r) : "f"(e + 1.0f));
    return fmaf(-2.0f, r, 1.0f);
}
__device__ __forceinline__ float fsig(float x) {
    return fmaf(0.5f, ftanh(0.5f * x), 0.5f);
}
__device__ __forceinline__ u32 smem_u32(const void* p) {
    u32 a;
    asm("{ .reg .u64 t; cvta.to.shared.u64 t, %1; cvt.u32.u64 %0, t; }"
        : "=r"(a) : "l"(p));
    return a;
}
__device__ __forceinline__ void hmma(float* d, const u32* a, u32 b0, u32 b1) {
    asm volatile("mma.sync.aligned.m16n8k16.row.col.f32.bf16.bf16.f32 "
        "{%0,%1,%2,%3}, {%4,%5,%6,%7}, {%8,%9}, {%0,%1,%2,%3};"
        : "+f"(d[0]), "+f"(d[1]), "+f"(d[2]), "+f"(d[3])
        : "r"(a[0]), "r"(a[1]), "r"(a[2]), "r"(a[3]), "r"(b0), "r"(b1));
}
__device__ __forceinline__ void ldsm4(u32* r, u32 addr) {
    asm volatile("ldmatrix.sync.aligned.m8n8.x4.shared.b16 {%0,%1,%2,%3}, [%4];"
        : "=r"(r[0]), "=r"(r[1]), "=r"(r[2]), "=r"(r[3]) : "r"(addr));
}
__device__ __forceinline__ void ldsm4t(u32* r, u32 addr) {
    asm volatile("ldmatrix.sync.aligned.m8n8.x4.trans.shared.b16 {%0,%1,%2,%3}, [%4];"
        : "=r"(r[0]), "=r"(r[1]), "=r"(r[2]), "=r"(r[3]) : "r"(addr));
}

// ------------------------------ setup ---------------------------------------
__global__ void __launch_bounds__(320) k_norm(const float* __restrict__ E) {
    __shared__ float sSum[10];
    int t = threadIdx.x;
    if (t < 10) sSum[t] = 0.f;
    __syncthreads();
    float e[10];
    if (t < NNODE) {
        float s = 0.f;
#pragma unroll
        for (int c = 0; c < 10; c++) { e[c] = E[t * 10 + c]; s += e[c] * e[c]; }
        float inv = rsqrtf(s);
#pragma unroll
        for (int c = 0; c < 10; c++) {
            e[c] *= inv;
            g_En[t * 10 + c] = e[c];
            atomicAdd(&sSum[c], e[c]);
        }
    }
    __syncthreads();
    if (t < NNODE) {
        float d = 0.f;
#pragma unroll
        for (int c = 0; c < 10; c++) d += e[c] * sSum[c];
        g_dinv[t] = rsqrtf(d);
    }
}

__global__ void k_lap() {
    int idx = blockIdx.x * 256 + threadIdx.x;
    if (idx >= NP * NP) return;
    int n = idx / NP, m = idx % NP;
    float v = 0.f;
    if (n < NNODE && m < NNODE) {
        float dot = 0.f;
#pragma unroll
        for (int c = 0; c < 10; c++) dot += g_En[n * 10 + c] * g_En[m * 10 + c];
        v = ((n == m) ? 1.f : 0.f) - g_dinv[n] * dot * g_dinv[m];
    }
    g_L[idx] = v;
    u32 bits = __float_as_uint(v);
    float res = v - __uint_as_float(bits & 0xFFFF0000u);
    u16 lo16;
    asm("cvt.rn.bf16.f32 %0, %1;" : "=h"(lo16) : "f"(res));
    g_Lhi[idx] = (u16)(bits >> 16);
    g_Llo[idx] = lo16;
}

__global__ void k_xt(const float* __restrict__ flow, float* __restrict__ Y0) {
    int idx = blockIdx.x * 128 + threadIdx.x;
    if (idx >= NP * BATCH) return;
    int n = idx >> 9, b = idx & 511;
#pragma unroll
    for (int c = 0; c < CIN; c++) {
        float v = 0.f;
        if (n < NNODE) v = flow[((size_t)b * NNODE + n) * CIN + c];
        Y0[(size_t)n * BC + b * CIN + c] = v;
    }
}

// ====== HMMA mainloop: 64x64 tile, 256 threads, K-split warp groups ========
// Sub-tile (bytes): Ah[64x24]=3072, Al=3072, Bh[16x72]=2304, Bl=2304 -> 10752.
// Stage = K32 pair = 2 sub-tiles = 21504. Two stages = 43008. 10 barriers.
// Warp group g (warps 4g..4g+3) computes K16-tiles with parity g -> partial acc.
#define HMMA_SUB 10752
#define HMMA_ST  21504
__device__ __forceinline__ void hmma_subcompute(
    u32 stg, int wl, int lane, float acc[8][4])
{
    u32 aoff = stg + (u32)((wl * 16 + (lane & 15)) * 48 + (lane >> 4) * 16);
    u32 ah[4], al[4];
    ldsm4(ah, aoff);
    ldsm4(al, aoff + 3072);
#pragma unroll
    for (int nt = 0; nt < 4; nt++) {
        u32 boff = stg + 6144 +
            (u32)((lane & 15) * 144 + (nt * 16 + ((lane >> 4) & 1) * 8) * 2);
        u32 bh[4], bl[4];
        ldsm4t(bh, boff);
        ldsm4t(bl, boff + 2304);
        hmma(acc[2 * nt],     ah, bh[0], bh[1]);
        hmma(acc[2 * nt],     ah, bl[0], bl[1]);
        hmma(acc[2 * nt],     al, bh[0], bh[1]);
        hmma(acc[2 * nt + 1], ah, bh[2], bh[3]);
        hmma(acc[2 * nt + 1], ah, bl[2], bl[3]);
        hmma(acc[2 * nt + 1], al, bh[2], bh[3]);
    }
}

__device__ __forceinline__ void hmma_mainloop(
    const float* __restrict__ Bsrc, int ld, int m0, int col0,
    char* smraw, float acc[8][4])
{
    int tid = threadIdx.x;
    int lane = tid & 31, warp = tid >> 5;
    int grp = warp >> 2, wl = warp & 3;       // compute group, warp-in-group
    int sub = tid >> 7, t2 = tid & 127;       // loader sub-tile, local tid
    int a_row = t2 >> 1, a_half = t2 & 1;
    int b_row = t2 >> 3, b_seg = t2 & 7;
    const u16* Aph = g_Lhi + (size_t)(m0 + a_row) * NP + a_half * 8;
    const u16* Apl = g_Llo + (size_t)(m0 + a_row) * NP + a_half * 8;
    const float* Bp = Bsrc + (size_t)b_row * ld + col0 + b_seg * 8;
    u32 smbase = smem_u32(smraw);

    // each thread loads K16-tile (2*tp + sub) into its sub-slot of stage st
    auto load_pair = [&](int tp, int st) {
        char* s0 = smraw + st * HMMA_ST + sub * HMMA_SUB;
        int k = 2 * tp + sub;
        uint4 vh = *(const uint4*)(Aph + k * 16);
        uint4 vl = *(const uint4*)(Apl + k * 16);
        const float* bp = Bp + (size_t)(k * 16) * ld;
        float4 f0 = ((const float4*)bp)[0];
        float4 f1 = ((const float4*)bp)[1];
        *(uint4*)(s0 + a_row * 48 + a_half * 16) = vh;
        *(uint4*)(s0 + 3072 + a_row * 48 + a_half * 16) = vl;
        float f[8] = {f0.x, f0.y, f0.z, f0.w, f1.x, f1.y, f1.z, f1.w};
        u32 hi[4], lo[4];
#pragma unroll
        for (int q = 0; q < 4; q++) {
            u32 ba = __float_as_uint(f[2 * q]);
            u32 bb = __float_as_uint(f[2 * q + 1]);
            asm("prmt.b32 %0, %1, %2, 0x7632;" : "=r"(hi[q]) : "r"(ba), "r"(bb));
            float ra = f[2 * q]     - __uint_as_float(ba & 0xFFFF0000u);
            float rb = f[2 * q + 1] - __uint_as_float(bb & 0xFFFF0000u);
            asm("cvt.rn.bf16x2.f32 %0, %1, %2;" : "=r"(lo[q]) : "f"(rb), "f"(ra));
        }
        *(uint4*)(s0 + 6144 + b_row * 144 + b_seg * 16) = make_uint4(hi[0], hi[1], hi[2], hi[3]);
        *(uint4*)(s0 + 8448 + b_row * 144 + b_seg * 16) = make_uint4(lo[0], lo[1], lo[2], lo[3]);
    };

    load_pair(0, 0);
    __syncthreads();

#pragma unroll 1
    for (int tp = 0; tp < 10; tp++) {
        int cur = tp & 1;
        if (tp < 9) load_pair(tp + 1, cur ^ 1);
        hmma_subcompute(smbase + cur * HMMA_ST + grp * HMMA_SUB, wl, lane, acc);
        __syncthreads();
    }
}

// stage this group's partial into o1s (group g at offset g*4608 floats)
__device__ __forceinline__ void stage_partial(
    float* o1s, int grp, int wl, int lane, const float acc[8][4])
{
    float* og = o1s + grp * 4608;
    int r0 = wl * 16 + (lane >> 2);
    int c = (lane & 3) * 2;
#pragma unroll
    for (int j = 0; j < 8; j++) {
        *(float2*)&og[r0 * 72 + j * 8 + c]       = make_float2(acc[j][0], acc[j][1]);
        *(float2*)&og[(r0 + 8) * 72 + j * 8 + c] = make_float2(acc[j][2], acc[j][3]);
    }
}

// ---- cheb: Cout = alpha*(L@Bin) + beta*Csub, HMMA path ---------------------
__global__ void __launch_bounds__(256) k_mm(
    const float* __restrict__ Bin, const float* __restrict__ Csub,
    float* __restrict__ Cout, int ld, float alpha, float beta)
{
    __shared__ __align__(16) char smraw[43008];
    int tid = threadIdx.x;
    int lane = tid & 31, warp = tid >> 5;
    int grp = warp >> 2, wl = warp & 3;
    int m0 = blockIdx.y * 64, col0 = blockIdx.x * 64;
    float acc[8][4];
#pragma unroll
    for (int j = 0; j < 8; j++)
#pragma unroll
        for (int q = 0; q < 4; q++) acc[j][q] = 0.f;
    hmma_mainloop(Bin, ld, m0, col0, smraw, acc);

    float* o1s = (float*)smraw;
    stage_partial(o1s, grp, wl, lane, acc);
    __syncthreads();

    // 256 items: r = tid>>2 (row), bl = tid&3 (16-col group)
    int r = tid >> 2, bl = tid & 3;
    size_t base = (size_t)(m0 + r) * ld + col0 + (bl << 4);
    const float* pa = o1s + r * 72 + (bl << 4);
    const float* pb = pa + 4608;
#pragma unroll
    for (int q = 0; q < 4; q++) {
        float4 cs = *(const float4*)(Csub + base + 4 * q);
        float4 w;
        w.x = alpha * (pa[4 * q + 0] + pb[4 * q + 0]) + beta * cs.x;
        w.y = alpha * (pa[4 * q + 1] + pb[4 * q + 1]) + beta * cs.y;
        w.z = alpha * (pa[4 * q + 2] + pb[4 * q + 2]) + beta * cs.z;
        w.w = alpha * (pa[4 * q + 3] + pb[4 * q + 3]) + beta * cs.w;
        *(float4*)(Cout + base + 4 * q) = w;
    }
}

// -------- combine: SB = sum_k Y_k @ cheb_w[k] + cheb_b ; SA = Y_0 @ cou_w ---
__global__ void __launch_bounds__(128) k_combine(
    const float* __restrict__ cheb_w, const float* __restrict__ cheb_b,
    const float* __restrict__ cou_w, const float* __restrict__ Y,
    float* __restrict__ SA, float* __restrict__ SB)
{
    __shared__ float scw[KORD * CIN * HID];
    __shared__ float scb[HID];
    __shared__ float sco[CIN * HID];
    int tid = threadIdx.x;
    for (int i = tid; i < KORD * CIN * HID; i += 128) scw[i] = cheb_w[i];
    if (tid < HID) scb[tid] = cheb_b[tid];
    if (tid < CIN * HID) sco[tid] = cou_w[tid];
    __syncthreads();
    int idx = blockIdx.x * 128 + tid;
    if (idx >= NP * BATCH) return;
    int n = idx >> 9, b = idx & 511;
    size_t base = (size_t)n * BH + (b << 4);
    if (n >= NNODE) {
#pragma unroll
        for (int h = 0; h < 16; h++) { SA[base + h] = 0.f; SB[base + h] = 0.f; }
        return;
    }
    float o[16], p[16];
#pragma unroll
    for (int h = 0; h < 16; h++) { o[h] = scb[h]; p[h] = 0.f; }
#pragma unroll
    for (int k = 0; k < KORD; k++) {
#pragma unroll
        for (int c = 0; c < CIN; c++) {
            float y = Y[(size_t)k * NPBC + (size_t)n * BC + b * CIN + c];
            const float* w = &scw[(k * CIN + c) * HID];
#pragma unroll
            for (int h = 0; h < 16; h++) o[h] = fmaf(y, w[h], o[h]);
            if (k == 0) {
#pragma unroll
                for (int h = 0; h < 16; h++) p[h] = fmaf(y, sco[c * HID + h], p[h]);
            }
        }
    }
#pragma unroll
    for (int h = 0; h < 16; h++) { SB[base + h] = o[h]; SA[base + h] = p[h]; }
}

// ======== GL via mma.sync bf16 split-precision ==============================
__global__ void __launch_bounds__(256) k_gl(
    const float* __restrict__ X, const float* __restrict__ A1,
    const float* __restrict__ A2,
    float* __restrict__ O1, float* __restrict__ O2,
    const float* __restrict__ w1, const float* __restrict__ w2,
    const float* __restrict__ w3, const float* __restrict__ b3, int mode)
{
    __shared__ __align__(16) char smraw[43008];
    __shared__ float sw1[256], sw2[256], sw3[256], sb3[16];
    int tid = threadIdx.x;
    int lane = tid & 31, warp = tid >> 5;
    int grp = warp >> 2, wl = warp & 3;
    if (tid < 256) { sw1[tid] = w1[tid]; sw2[tid] = w2[tid]; sw3[tid] = w3[tid]; }
    if (tid < 16) sb3[tid] = b3[tid];

    int m0 = blockIdx.y * 64, col0 = blockIdx.x * 64;
    float acc[8][4];
#pragma unroll
    for (int j = 0; j < 8; j++)
#pragma unroll
        for (int q = 0; q < 4; q++) acc[j][q] = 0.f;
    hmma_mainloop(X, BH, m0, col0, smraw, acc);

    float* o1s = (float*)smraw;
    stage_partial(o1s, grp, wl, lane, acc);
    __syncthreads();

    // epilogue: 256 items = 64 rows x 4 col-groups ; 1 per thread
    {
        int r = tid >> 2, bl = tid & 3;
        size_t base = (size_t)(m0 + r) * BH + col0 + (bl << 4);
        float xv[16];
#pragma unroll
        for (int q = 0; q < 4; q++) {
            float4 v = *(const float4*)(X + base + 4 * q);
            xv[4 * q] = v.x; xv[4 * q + 1] = v.y; xv[4 * q + 2] = v.z; xv[4 * q + 3] = v.w;
        }
        float a1v[16];
#pragma unroll 4
        for (int p = 0; p < 16; p++) {
            float s = 0.f;
#pragma unroll
            for (int h = 0; h < 16; h++) s = fmaf(xv[h], sw1[h * 16 + p], s);
            a1v[p] = ftanh(s);
        }
        float a2v[16];
#pragma unroll 4
        for (int p = 0; p < 16; p++) {
            float s = 0.f;
#pragma unroll
            for (int h = 0; h < 16; h++) s = fmaf(a1v[h], sw2[h * 16 + p], s);
            a2v[p] = ftanh(s);
        }
        float rr[16];
        const float* pa = o1s + r * 72 + (bl << 4);
        const float* pb = pa + 4608;
#pragma unroll
        for (int h = 0; h < 16; h++) rr[h] = pa[h] + pb[h] - a2v[h];
        if (mode == 0) {
#pragma unroll 4
            for (int p = 0; p < 16; p++) {
                float s = sb3[p];
#pragma unroll
                for (int h = 0; h < 16; h++) s = fmaf(rr[h], sw3[h * 16 + p], s);
                O1[base + p] = s;
                O2[base + p] = A1[base + p] + 2.0f * s;
            }
        } else {
#pragma unroll 4
            for (int p = 0; p < 16; p++) {
                float s = sb3[p];
#pragma unroll
                for (int h = 0; h < 16; h++) s = fmaf(rr[h], sw3[h * 16 + p], s);
                O1[base + p] = A1[base + p] + 0.5f * A2[base + p] + 0.5f * s;
            }
        }
    }
}

// ---------------- 16x16 matmul helper with f32x2 ----------------------------
__device__ __forceinline__ void mm16_f2(const float* x, const float* Wsh,
                                        const ull* bias2, float* out)
{
    const ull* W2 = (const ull*)Wsh;
    ull xs[16];
#pragma unroll
    for (int h = 0; h < 16; h++) xs[h] = pack2(x[h], x[h]);
#pragma unroll
    for (int pp = 0; pp < 8; pp++) {
        ull s = bias2 ? bias2[pp] : pack2(0.f, 0.f);
#pragma unroll
        for (int h = 0; h < 16; h++) s = fma2(xs[h], W2[h * 8 + pp], s);
        unpack2(s, out[2 * pp], out[2 * pp + 1]);
    }
}

// ---------------- NL: fused 10-step LSTM-cell chain (f32x2) -----------------
__device__ __forceinline__ void nl_eval(
    const float* x, float* out,
    const ull* W2, const ull* sb2, const ull* w22)
{
    ull xs[16];
#pragma unroll
    for (int h = 0; h < 16; h++) xs[h] = pack2(x[h], x[h]);
    ull acc2[8];
#pragma unroll
    for (int q = 0; q < 8; q++) acc2[q] = pack2(0.f, 0.f);
#pragma unroll 1
    for (int pp = 0; pp < 16; pp++) {
        ull gi = sb2[pp], gg = sb2[32 + pp], go = sb2[48 + pp];
#pragma unroll
        for (int h = 0; h < 16; h++) {
            gi = fma2(xs[h], W2[h * 64 + pp], gi);
            gg = fma2(xs[h], W2[h * 64 + 32 + pp], gg);
            go = fma2(xs[h], W2[h * 64 + 48 + pp], go);
        }
        float gi0, gi1, gg0, gg1, go0, go1;
        unpack2(gi, gi0, gi1); unpack2(gg, gg0, gg1); unpack2(go, go0, go1);
        float c0 = fsig(gi0) * ftanh(gg0);
        float th0 = ftanh(fsig(go0) * ftanh(c0));
        float c1 = fsig(gi1) * ftanh(gg1);
        float th1 = ftanh(fsig(go1) * ftanh(c1));
        ull t0 = pack2(th0, th0), t1 = pack2(th1, th1);
#pragma unroll
        for (int q = 0; q < 8; q++) {
            acc2[q] = fma2(t0, w22[(2 * pp) * 8 + q], acc2[q]);
            acc2[q] = fma2(t1, w22[(2 * pp + 1) * 8 + q], acc2[q]);
        }
    }
#pragma unroll
    for (int q = 0; q < 8; q++) unpack2(acc2[q], out[2 * q], out[2 * q + 1]);
}

__global__ void __launch_bounds__(128) k_nl(
    const float* __restrict__ S0, const float* __restrict__ S1,
    const float* __restrict__ Wih, const float* __restrict__ lb,
    const float* __restrict__ w2, const float* __restrict__ cw,
    const float* __restrict__ cb, const float* __restrict__ c1w,
    const float* __restrict__ c1b, float* __restrict__ out)
{
    __shared__ __align__(16) float sW[16 * 128];
    __shared__ __align__(16) float sb[128];
    __shared__ __align__(16) float sw2[32 * 16];
    __shared__ __align__(16) float scw[256], sc1w[256];
    __shared__ __align__(16) float scb[16], sc1b[16];
    int tid = threadIdx.x;
    for (int i = tid; i < 2048; i += 128) sW[i] = Wih[i];
    sb[tid] = lb[tid];
    for (int i = tid; i < 512; i += 128) sw2[i] = w2[i];
    for (int i = tid; i < 256; i += 128) { scw[i] = cw[i]; sc1w[i] = c1w[i]; }
    if (tid < 16) { scb[tid] = cb[tid]; sc1b[tid] = c1b[tid]; }
    __syncthreads();
    const ull* W2  = (const ull*)sW;
    const ull* sb2 = (const ull*)sb;
    const ull* w22 = (const ull*)sw2;

    int idx = blockIdx.x * 128 + tid;
    int n = idx >> 9, b = idx & 511;
    size_t base = (size_t)n * BH + ((size_t)b << 4);
    float s0[16], s1[16];
#pragma unroll
    for (int q = 0; q < 4; q++) {
        float4 t0 = *(const float4*)(S0 + base + 4 * q);
        float4 t1 = *(const float4*)(S1 + base + 4 * q);
        s0[4 * q] = t0.x; s0[4 * q + 1] = t0.y; s0[4 * q + 2] = t0.z; s0[4 * q + 3] = t0.w;
        s1[4 * q] = t1.x; s1[4 * q + 1] = t1.y; s1[4 * q + 2] = t1.z; s1[4 * q + 3] = t1.w;
    }
    float s00[16], s11[16];
    mm16_f2(s0, scw, (const ull*)scb, s00);
    mm16_f2(s1, sc1w, (const ull*)sc1b, s11);
    float* op = out + (((size_t)b * NNODE + n) * 10) * HID;
    float t[16], tmp[16], g[16], p2[16];
    nl_eval(s11, t, W2, sb2, w22);
#pragma unroll
    for (int h = 0; h < 16; h++) tmp[h] = fmaf(2.0f, t[h], s00[h]);
    nl_eval(tmp, tmp, W2, sb2, w22);
#pragma unroll
    for (int h = 0; h < 16; h++) {
        g[h] = fmaf(0.5f, t[h], s1[h]) + 0.5f * tmp[h];
        p2[h] = s11[h];
    }
#pragma unroll
    for (int q = 0; q < 4; q++)
        *(float4*)(op + 4 * q) = make_float4(g[4 * q], g[4 * q + 1], g[4 * q + 2], g[4 * q + 3]);
#pragma unroll 1
    for (int j = 1; j < 10; j++) {
        nl_eval(g, t, W2, sb2, w22);
#pragma unroll
        for (int h = 0; h < 16; h++) tmp[h] = fmaf(2.0f, t[h], p2[h]);
        nl_eval(tmp, tmp, W2, sb2, w22);
#pragma unroll
        for (int h = 0; h < 16; h++) {
            float nw = fmaf(0.5f, t[h], g[h]) + 0.5f * tmp[h];
            p2[h] = g[h];
            g[h] = nw;
        }
        float* oj = op + (size_t)j * HID;
#pragma unroll
        for (int q = 0; q < 4; q++)
            *(float4*)(oj + 4 * q) = make_float4(g[4 * q], g[4 * q + 1], g[4 * q + 2], g[4 * q + 3]);
    }
}

// ------------------------------ launch --------------------------------------
extern "C" void kernel_launch(void* const* d_in, const int* in_sizes, int n_in,
                              void* d_out, int out_size) {
    const float* flow    = (const float*)d_in[0];
    const float* nodeemb = (const float*)d_in[1];
    const float* cheb_w  = (const float*)d_in[2];
    const float* cheb_b  = (const float*)d_in[3];
    const float* cou_w   = (const float*)d_in[4];
    const float* gl_out  = (const float*)d_in[5];
    const float* gl_fk   = (const float*)d_in[6];
    const float* gl_tz_w = (const float*)d_in[7];
    const float* gl_tz_b = (const float*)d_in[8];
    const float* lstmW   = (const float*)d_in[9];
    const float* lstmb   = (const float*)d_in[10];
    const float* nl_w2   = (const float*)d_in[11];
    const float* c_w     = (const float*)d_in[12];
    const float* c_b     = (const float*)d_in[13];
    const float* c1_w    = (const float*)d_in[14];
    const float* c1_b    = (const float*)d_in[15];

    float *Y, *SA, *SB, *T, *U;
    cudaGetSymbolAddress((void**)&Y,  g_Y);
    cudaGetSymbolAddress((void**)&SA, g_SA);
    cudaGetSymbolAddress((void**)&SB, g_SB);
    cudaGetSymbolAddress((void**)&T,  g_T);
    cudaGetSymbolAddress((void**)&U,  g_U);

    k_xt<<<(NP * BATCH + 127) / 128, 128>>>(flow, Y);
    k_norm<<<1, 320>>>(nodeemb);
    k_lap<<<(NP * NP + 255) / 256, 256>>>();

    // Chebyshev feature recurrence on tensor cores
    dim3 cgrid(BC / 64, NP / 64);
    k_mm<<<cgrid, 256>>>(Y, Y, Y + NPBC, BC, 1.f, 0.f);
    for (int k = 2; k < KORD; k++)
        k_mm<<<cgrid, 256>>>(
            Y + (size_t)(k - 1) * NPBC, Y + (size_t)(k - 2) * NPBC,
            Y + (size_t)k * NPBC, BC, 2.f, -1.f);

    k_combine<<<(NP * BATCH + 127) / 128, 128>>>(cheb_w, cheb_b, cou_w, Y, SA, SB);

    // GL diffusion chain (HMMA path)
    float* p = SA;
    float* c = SB;
    dim3 glgrid(BH / 64, NP / 64);
    for (int it = 0; it < 10; it++) {
        k_gl<<<glgrid, 256>>>(c, p, p, T, U, gl_out, gl_fk, gl_tz_w, gl_tz_b, 0);
        k_gl<<<glgrid, 256>>>(U, c, T, p, T, gl_out, gl_fk, gl_tz_w, gl_tz_b, 1);
        float* tmpp = p; p = c; c = tmpp;
    }
    // after 10 iters: step_0 = p, step_1 = c

    k_nl<<<(NNODE * BATCH) / 128, 128>>>(p, c, lstmW, lstmb, nl_w2,
                                         c_w, c_b, c1_w, c1_b, (float*)d_out);
}